// round 3
// baseline (speedup 1.0000x reference)
#include <cuda_runtime.h>
#include <cuda_bf16.h>

// Problem constants (fixed shapes for this dataset)
#define BATCH   4
#define NPTS    16384
#define MPTS    4096
#define C1DIM   128
#define C2DIM   256
#define CIN     384       // C1 + C2
#define H1DIM   256
#define H2DIM   256
#define COUT    128
#define TOTAL   (BATCH * NPTS)   // 65536 points

// ---------------------------------------------------------------------------
// Scratch (static device globals — no runtime allocation allowed)
// ---------------------------------------------------------------------------
__device__ int   g_idx[TOTAL * 3];
__device__ float g_w[TOTAL * 3];
__device__ float g_X[(size_t)TOTAL * CIN];     // ~100 MB
__device__ float g_Ha[(size_t)TOTAL * H1DIM];  // ~67 MB
__device__ float g_Hb[(size_t)TOTAL * H2DIM];  // ~67 MB

// ---------------------------------------------------------------------------
// Kernel 1: three_nn + interpolation weights
// One block = 256 query points of one batch; xyz2 of that batch staged in smem.
// ---------------------------------------------------------------------------
__global__ __launch_bounds__(256) void three_nn_kernel(
    const float* __restrict__ xyz1, const float* __restrict__ xyz2)
{
    __shared__ float sx[MPTS];
    __shared__ float sy[MPTS];
    __shared__ float sz[MPTS];

    const int b = blockIdx.y;
    const float* p2 = xyz2 + (size_t)b * MPTS * 3;
    for (int j = threadIdx.x; j < MPTS; j += 256) {
        sx[j] = p2[3 * j + 0];
        sy[j] = p2[3 * j + 1];
        sz[j] = p2[3 * j + 2];
    }
    __syncthreads();

    const int n = blockIdx.x * 256 + threadIdx.x;
    const float* p1 = xyz1 + ((size_t)b * NPTS + n) * 3;
    const float x = p1[0], y = p1[1], z = p1[2];

    float d0 = 1e30f, d1 = 1e30f, d2 = 1e30f;
    int   i0 = 0, i1 = 0, i2 = 0;

#pragma unroll 4
    for (int j = 0; j < MPTS; j++) {
        float dx = x - sx[j];
        float dy = y - sy[j];
        float dz = z - sz[j];
        float d = dx * dx + dy * dy + dz * dz;
        if (d < d2) {
            if (d < d1) {
                d2 = d1; i2 = i1;
                if (d < d0) { d1 = d0; i1 = i0; d0 = d; i0 = j; }
                else        { d1 = d;  i1 = j; }
            } else {
                d2 = d; i2 = j;
            }
        }
    }

    float r0 = 1.0f / fmaxf(d0, 1e-10f);
    float r1 = 1.0f / fmaxf(d1, 1e-10f);
    float r2 = 1.0f / fmaxf(d2, 1e-10f);
    float s = 1.0f / (r0 + r1 + r2);

    size_t o = ((size_t)b * NPTS + n) * 3;
    g_idx[o + 0] = i0; g_idx[o + 1] = i1; g_idx[o + 2] = i2;
    g_w[o + 0] = r0 * s; g_w[o + 1] = r1 * s; g_w[o + 2] = r2 * s;
}

// ---------------------------------------------------------------------------
// Kernel 2: build X = concat(features1, three_interpolate(features2))
// One block per point; 384 threads = one output channel each.
// ---------------------------------------------------------------------------
__global__ __launch_bounds__(384) void build_x_kernel(
    const float* __restrict__ f1, const float* __restrict__ f2)
{
    const int p = blockIdx.x;     // 0 .. TOTAL-1
    const int t = threadIdx.x;    // 0 .. 383

    if (t < C1DIM) {
        g_X[(size_t)p * CIN + t] = f1[(size_t)p * C1DIM + t];
    } else {
        const int c = t - C1DIM;
        const int b = p >> 14;    // NPTS = 16384
        const size_t o = (size_t)p * 3;
        const int i0 = g_idx[o], i1 = g_idx[o + 1], i2 = g_idx[o + 2];
        const float w0 = g_w[o], w1 = g_w[o + 1], w2 = g_w[o + 2];
        const float* base = f2 + (size_t)b * MPTS * C2DIM;
        float v = w0 * base[(size_t)i0 * C2DIM + c]
                + w1 * base[(size_t)i1 * C2DIM + c]
                + w2 * base[(size_t)i2 * C2DIM + c];
        g_X[(size_t)p * CIN + C1DIM + c] = v;
    }
}

// ---------------------------------------------------------------------------
// Kernel 3: fp32 SGEMM with packed f32x2 FFMA, fused bias (+ optional ReLU)
// C[M,N] = A[M,K] @ W[K,N] + bias.  Block tile 64x128, thread tile 4x8.
// ---------------------------------------------------------------------------
__device__ __forceinline__ unsigned long long splat2(float a) {
    unsigned long long r;
    unsigned int u = __float_as_uint(a);
    asm("mov.b64 %0, {%1, %2};" : "=l"(r) : "r"(u), "r"(u));
    return r;
}
__device__ __forceinline__ void fma2(unsigned long long& d,
                                     unsigned long long a,
                                     unsigned long long b) {
    asm("fma.rn.f32x2 %0, %1, %2, %3;" : "=l"(d) : "l"(a), "l"(b), "l"(d));
}

__global__ __launch_bounds__(256, 2) void gemm_bias_act(
    const float* __restrict__ A, const float* __restrict__ W,
    const float* __restrict__ bias, float* __restrict__ C,
    int M, int K, int N, int doRelu)
{
    __shared__ __align__(16) float As[8][64];    // [k][m]
    __shared__ __align__(16) float Bs[8][128];   // [k][n]

    const int tid = threadIdx.x;
    const int tx = tid & 15;     // 0..15 -> 8 columns each
    const int ty = tid >> 4;     // 0..15 -> 4 rows each
    const int m0 = blockIdx.y * 64;
    const int n0 = blockIdx.x * 128;

    // Load mappings
    const int arow = tid >> 2;          // 0..63
    const int acol = (tid & 3) << 1;    // 0,2,4,6
    const int brow = tid >> 5;          // 0..7
    const int bcol = (tid & 31) << 2;   // 0..124

    const float* Ap = A + (size_t)(m0 + arow) * K + acol;
    const float* Wp = W + (size_t)brow * N + n0 + bcol;

    unsigned long long acc[4][4];
#pragma unroll
    for (int i = 0; i < 4; i++)
#pragma unroll
        for (int j = 0; j < 4; j++) acc[i][j] = 0ULL;  // (+0.f, +0.f)

    for (int k0 = 0; k0 < K; k0 += 8) {
        float2 av = *(const float2*)(Ap + k0);
        float4 bv = *(const float4*)(Wp + (size_t)k0 * N);
        As[acol][arow]     = av.x;
        As[acol + 1][arow] = av.y;
        *(float4*)&Bs[brow][bcol] = bv;
        __syncthreads();

#pragma unroll
        for (int k = 0; k < 8; k++) {
            float4 a = *(const float4*)&As[k][ty << 2];
            const float* brow_ptr = &Bs[k][tx << 3];
            ulonglong2 b01 = *(const ulonglong2*)brow_ptr;
            ulonglong2 b23 = *(const ulonglong2*)(brow_ptr + 4);
            unsigned long long a2[4];
            a2[0] = splat2(a.x); a2[1] = splat2(a.y);
            a2[2] = splat2(a.z); a2[3] = splat2(a.w);
            unsigned long long bb[4] = {b01.x, b01.y, b23.x, b23.y};
#pragma unroll
            for (int i = 0; i < 4; i++)
#pragma unroll
                for (int j = 0; j < 4; j++)
                    fma2(acc[i][j], a2[i], bb[j]);
        }
        __syncthreads();
    }

    // Epilogue: bias + optional ReLU, vectorized stores
    float bvals[8];
#pragma unroll
    for (int j = 0; j < 8; j++) bvals[j] = bias[n0 + (tx << 3) + j];

#pragma unroll
    for (int i = 0; i < 4; i++) {
        const int row = m0 + (ty << 2) + i;
        float* Cp = C + (size_t)row * N + n0 + (tx << 3);
        float outv[8];
#pragma unroll
        for (int j = 0; j < 4; j++) {
            float lo = __uint_as_float((unsigned)(acc[i][j] & 0xffffffffULL));
            float hi = __uint_as_float((unsigned)(acc[i][j] >> 32));
            lo += bvals[2 * j];
            hi += bvals[2 * j + 1];
            if (doRelu) { lo = fmaxf(lo, 0.0f); hi = fmaxf(hi, 0.0f); }
            outv[2 * j] = lo; outv[2 * j + 1] = hi;
        }
        *(float4*)Cp       = make_float4(outv[0], outv[1], outv[2], outv[3]);
        *(float4*)(Cp + 4) = make_float4(outv[4], outv[5], outv[6], outv[7]);
    }
}

// ---------------------------------------------------------------------------
// Launch
// ---------------------------------------------------------------------------
extern "C" void kernel_launch(void* const* d_in, const int* in_sizes, int n_in,
                              void* d_out, int out_size)
{
    const float* xyz1 = (const float*)d_in[0];
    const float* xyz2 = (const float*)d_in[1];
    const float* f1   = (const float*)d_in[2];
    const float* f2   = (const float*)d_in[3];
    const float* W1   = (const float*)d_in[4];
    const float* b1   = (const float*)d_in[5];
    const float* W2   = (const float*)d_in[6];
    const float* b2   = (const float*)d_in[7];
    const float* W3   = (const float*)d_in[8];
    const float* b3   = (const float*)d_in[9];
    float* out = (float*)d_out;

    void *xp, *hap, *hbp;
    cudaGetSymbolAddress(&xp,  g_X);
    cudaGetSymbolAddress(&hap, g_Ha);
    cudaGetSymbolAddress(&hbp, g_Hb);
    float* Xp  = (float*)xp;
    float* Hap = (float*)hap;
    float* Hbp = (float*)hbp;

    dim3 g1(NPTS / 256, BATCH);
    three_nn_kernel<<<g1, 256>>>(xyz1, xyz2);

    build_x_kernel<<<TOTAL, 384>>>(f1, f2);

    gemm_bias_act<<<dim3(H1DIM / 128, TOTAL / 64), 256>>>(Xp,  W1, b1, Hap, TOTAL, CIN,   H1DIM, 1);
    gemm_bias_act<<<dim3(H2DIM / 128, TOTAL / 64), 256>>>(Hap, W2, b2, Hbp, TOTAL, H1DIM, H2DIM, 1);
    gemm_bias_act<<<dim3(COUT  / 128, TOTAL / 64), 256>>>(Hbp, W3, b3, out, TOTAL, H2DIM, COUT,  0);
}

// round 6
// speedup vs baseline: 2.4278x; 2.4278x over previous
#include <cuda_runtime.h>
#include <cuda_bf16.h>
#include <cstdint>

// Problem constants (fixed shapes for this dataset)
#define BATCH   4
#define NPTS    16384
#define MPTS    4096
#define C1DIM   128
#define C2DIM   256
#define CIN     384       // C1 + C2
#define H1DIM   256
#define H2DIM   256
#define COUT    128
#define TOTAL   (BATCH * NPTS)   // 65536 points

// ---------------------------------------------------------------------------
// Scratch (static device globals — no runtime allocation allowed)
// ---------------------------------------------------------------------------
__device__ int   g_idx[TOTAL * 3];
__device__ float g_w[TOTAL * 3];
__device__ __align__(256) __nv_bfloat16 g_Xh[(size_t)TOTAL * CIN];
__device__ __align__(256) __nv_bfloat16 g_Xl[(size_t)TOTAL * CIN];
__device__ __align__(256) __nv_bfloat16 g_Hah[(size_t)TOTAL * H1DIM];
__device__ __align__(256) __nv_bfloat16 g_Hal[(size_t)TOTAL * H1DIM];
__device__ __align__(256) __nv_bfloat16 g_Hbh[(size_t)TOTAL * H2DIM];
__device__ __align__(256) __nv_bfloat16 g_Hbl[(size_t)TOTAL * H2DIM];
__device__ __align__(256) __nv_bfloat16 g_W1h[H1DIM * CIN];
__device__ __align__(256) __nv_bfloat16 g_W1l[H1DIM * CIN];
__device__ __align__(256) __nv_bfloat16 g_W2h[H2DIM * H1DIM];
__device__ __align__(256) __nv_bfloat16 g_W2l[H2DIM * H1DIM];
__device__ __align__(256) __nv_bfloat16 g_W3h[COUT * H2DIM];
__device__ __align__(256) __nv_bfloat16 g_W3l[COUT * H2DIM];

// ---------------------------------------------------------------------------
// Small helpers
// ---------------------------------------------------------------------------
__device__ __forceinline__ uint32_t smem_to_u32(const void* p) {
    uint32_t a;
    asm("{ .reg .u64 t; cvta.to.shared.u64 t, %1; cvt.u32.u64 %0, t; }"
        : "=r"(a) : "l"(p));
    return a;
}
__device__ __forceinline__ void cpa16(uint32_t dst, const void* src) {
    asm volatile("cp.async.cg.shared.global [%0], [%1], 16;"
                 :: "r"(dst), "l"(src));
}
__device__ __forceinline__ void cpa_commit() {
    asm volatile("cp.async.commit_group;" ::: "memory");
}
template <int N>
__device__ __forceinline__ void cpa_wait() {
    asm volatile("cp.async.wait_group %0;" :: "n"(N) : "memory");
}
__device__ __forceinline__ uint32_t lds32(uint32_t addr) {
    uint32_t v;
    asm("ld.shared.b32 %0, [%1];" : "=r"(v) : "r"(addr));
    return v;
}
// m16n8k16 row.col bf16 MMA, f32 accumulate
__device__ __forceinline__ void mma_bf16(float* d, const uint32_t* a,
                                         const uint32_t* b) {
    asm("mma.sync.aligned.m16n8k16.row.col.f32.bf16.bf16.f32 "
        "{%0,%1,%2,%3}, {%4,%5,%6,%7}, {%8,%9}, {%0,%1,%2,%3};"
        : "+f"(d[0]), "+f"(d[1]), "+f"(d[2]), "+f"(d[3])
        : "r"(a[0]), "r"(a[1]), "r"(a[2]), "r"(a[3]), "r"(b[0]), "r"(b[1]));
}
// fp32 -> bf16 hi/lo split
__device__ __forceinline__ void split_bf16(float x, __nv_bfloat16& h,
                                           __nv_bfloat16& l) {
    h = __float2bfloat16_rn(x);
    l = __float2bfloat16_rn(x - __bfloat162float(h));
}

// ---------------------------------------------------------------------------
// Kernel 1: three_nn + interpolation weights (unchanged, passing)
// ---------------------------------------------------------------------------
__global__ __launch_bounds__(256) void three_nn_kernel(
    const float* __restrict__ xyz1, const float* __restrict__ xyz2)
{
    __shared__ float sx[MPTS];
    __shared__ float sy[MPTS];
    __shared__ float sz[MPTS];

    const int b = blockIdx.y;
    const float* p2 = xyz2 + (size_t)b * MPTS * 3;
    for (int j = threadIdx.x; j < MPTS; j += 256) {
        sx[j] = p2[3 * j + 0];
        sy[j] = p2[3 * j + 1];
        sz[j] = p2[3 * j + 2];
    }
    __syncthreads();

    const int n = blockIdx.x * 256 + threadIdx.x;
    const float* p1 = xyz1 + ((size_t)b * NPTS + n) * 3;
    const float x = p1[0], y = p1[1], z = p1[2];

    float d0 = 1e30f, d1 = 1e30f, d2 = 1e30f;
    int   i0 = 0, i1 = 0, i2 = 0;

#pragma unroll 4
    for (int j = 0; j < MPTS; j++) {
        float dx = x - sx[j];
        float dy = y - sy[j];
        float dz = z - sz[j];
        float d = dx * dx + dy * dy + dz * dz;
        if (d < d2) {
            if (d < d1) {
                d2 = d1; i2 = i1;
                if (d < d0) { d1 = d0; i1 = i0; d0 = d; i0 = j; }
                else        { d1 = d;  i1 = j; }
            } else {
                d2 = d; i2 = j;
            }
        }
    }

    float r0 = 1.0f / fmaxf(d0, 1e-10f);
    float r1 = 1.0f / fmaxf(d1, 1e-10f);
    float r2 = 1.0f / fmaxf(d2, 1e-10f);
    float s = 1.0f / (r0 + r1 + r2);

    size_t o = ((size_t)b * NPTS + n) * 3;
    g_idx[o + 0] = i0; g_idx[o + 1] = i1; g_idx[o + 2] = i2;
    g_w[o + 0] = r0 * s; g_w[o + 1] = r1 * s; g_w[o + 2] = r2 * s;
}

// ---------------------------------------------------------------------------
// Kernel 2: build X = concat(features1, interp(features2)), split to bf16 h/l
// ---------------------------------------------------------------------------
__global__ __launch_bounds__(384) void build_x_kernel(
    const float* __restrict__ f1, const float* __restrict__ f2)
{
    const int p = blockIdx.x;
    const int t = threadIdx.x;
    float v;

    if (t < C1DIM) {
        v = f1[(size_t)p * C1DIM + t];
    } else {
        const int c = t - C1DIM;
        const int b = p >> 14;
        const size_t o = (size_t)p * 3;
        const int i0 = g_idx[o], i1 = g_idx[o + 1], i2 = g_idx[o + 2];
        const float w0 = g_w[o], w1 = g_w[o + 1], w2 = g_w[o + 2];
        const float* base = f2 + (size_t)b * MPTS * C2DIM;
        v = w0 * base[(size_t)i0 * C2DIM + c]
          + w1 * base[(size_t)i1 * C2DIM + c]
          + w2 * base[(size_t)i2 * C2DIM + c];
    }
    __nv_bfloat16 h, l;
    split_bf16(v, h, l);
    g_Xh[(size_t)p * CIN + t] = h;
    g_Xl[(size_t)p * CIN + t] = l;
}

// ---------------------------------------------------------------------------
// Kernel 2b: weight prep — transpose [K,N]->[N,K] and split to bf16 h/l
// ---------------------------------------------------------------------------
__global__ void prep_w_kernel(const float* __restrict__ W,
                              __nv_bfloat16* __restrict__ Wh,
                              __nv_bfloat16* __restrict__ Wl, int K, int N)
{
    int i = blockIdx.x * 256 + threadIdx.x;
    if (i < N * K) {
        int n = i / K, k = i - n * K;
        __nv_bfloat16 h, l;
        split_bf16(W[(size_t)k * N + n], h, l);
        Wh[i] = h; Wl[i] = l;
    }
}

// ---------------------------------------------------------------------------
// Kernel 3: bf16 HMMA GEMM (mma.sync m16n8k16), 3-pass fp32 emulation.
// C[M,Ntot] = A[M,K] @ Bt[Ntot,K]^T + bias (opt ReLU).
// A = Ah + Al, B = Bh + Bl (bf16);  D = AhBh + AhBl + AlBh.
// CTA 128x128, BK=32, 8 warps (4m x 2n), warp tile 32x64.
// smem row stride 80B -> conflict-free fragment loads.
// ---------------------------------------------------------------------------
#define BM 128
#define BN 128
#define BK 32
#define SROW 80                       // bytes per smem row (32 bf16 + pad)
#define TILEB (128 * SROW)            // 10240 per operand tile
#define BUFB  (4 * TILEB)             // Ah, Al, Bh, Bl per buffer
#define GEMM_SMEM (2 * BUFB)          // 81920

__device__ __forceinline__ void load_chunk(
    uint32_t sbuf,
    const __nv_bfloat16* __restrict__ Ah, const __nv_bfloat16* __restrict__ Al,
    const __nv_bfloat16* __restrict__ Bh, const __nv_bfloat16* __restrict__ Bl,
    int K, int tid)
{
    const int row = tid >> 2;         // 0..63
    const int piece = tid & 3;        // 0..3 (16B each, 64B row payload)
    const uint32_t d0 = row * SROW + piece * 16;
    const size_t g0 = (size_t)row * K + piece * 8;
    const uint32_t d1 = d0 + 64 * SROW;
    const size_t g1 = g0 + (size_t)64 * K;

    cpa16(sbuf + 0 * TILEB + d0, Ah + g0);
    cpa16(sbuf + 1 * TILEB + d0, Al + g0);
    cpa16(sbuf + 2 * TILEB + d0, Bh + g0);
    cpa16(sbuf + 3 * TILEB + d0, Bl + g0);
    cpa16(sbuf + 0 * TILEB + d1, Ah + g1);
    cpa16(sbuf + 1 * TILEB + d1, Al + g1);
    cpa16(sbuf + 2 * TILEB + d1, Bh + g1);
    cpa16(sbuf + 3 * TILEB + d1, Bl + g1);
}

__global__ __launch_bounds__(256, 2) void gemm_tc(
    const __nv_bfloat16* __restrict__ Ah, const __nv_bfloat16* __restrict__ Al,
    const __nv_bfloat16* __restrict__ Bh, const __nv_bfloat16* __restrict__ Bl,
    const float* __restrict__ bias,
    float* __restrict__ Cf,
    __nv_bfloat16* __restrict__ Ch, __nv_bfloat16* __restrict__ Cl,
    int K, int Ntot, int doRelu, int outBf16)
{
    extern __shared__ char smem[];
    const uint32_t sb = smem_to_u32(smem);
    const int tid = threadIdx.x;
    const int wid = tid >> 5;
    const int lane = tid & 31;
    const int gid = lane >> 2;        // 0..7
    const int tig = lane & 3;         // 0..3
    const int warp_m = wid >> 1;      // 0..3
    const int warp_n = wid & 1;       // 0..1
    const int m0 = blockIdx.y * BM;
    const int n0 = blockIdx.x * BN;

    const __nv_bfloat16* Ahp = Ah + (size_t)m0 * K;
    const __nv_bfloat16* Alp = Al + (size_t)m0 * K;
    const __nv_bfloat16* Bhp = Bh + (size_t)n0 * K;
    const __nv_bfloat16* Blp = Bl + (size_t)n0 * K;

    float acc[2][8][4];
#pragma unroll
    for (int t = 0; t < 2; t++)
#pragma unroll
        for (int nt = 0; nt < 8; nt++)
#pragma unroll
            for (int r = 0; r < 4; r++) acc[t][nt][r] = 0.0f;

    const int nch = K / BK;

    // prologue: prefetch chunks 0 and 1
    load_chunk(sb, Ahp, Alp, Bhp, Blp, K, tid);
    cpa_commit();
    if (nch > 1) {
        load_chunk(sb + BUFB, Ahp + BK, Alp + BK, Bhp + BK, Blp + BK, K, tid);
        cpa_commit();
    }

    for (int c = 0; c < nch; c++) {
        if (c + 1 < nch) cpa_wait<1>(); else cpa_wait<0>();
        __syncthreads();

        const uint32_t sA = sb + (c & 1) * BUFB;
        const uint32_t sB = sA + 2 * TILEB;

#pragma unroll
        for (int s = 0; s < 2; s++) {             // two k16 steps per chunk
            // A fragments: 2 m-tiles x (hi,lo) x 4 regs
            uint32_t aF[2][2][4];
#pragma unroll
            for (int t = 0; t < 2; t++) {
                const uint32_t base =
                    sA + (warp_m * 32 + t * 16 + gid) * SROW + s * 32 + tig * 4;
#pragma unroll
                for (int hl = 0; hl < 2; hl++) {
                    const uint32_t b2 = base + hl * TILEB;
                    aF[t][hl][0] = lds32(b2);
                    aF[t][hl][1] = lds32(b2 + 8 * SROW);
                    aF[t][hl][2] = lds32(b2 + 16);
                    aF[t][hl][3] = lds32(b2 + 8 * SROW + 16);
                }
            }
#pragma unroll
            for (int nh = 0; nh < 2; nh++) {      // 2 halves of 4 n-tiles
                uint32_t bF[4][2][2];
#pragma unroll
                for (int j = 0; j < 4; j++) {
                    const int nt = nh * 4 + j;
                    const uint32_t base =
                        sB + (warp_n * 64 + nt * 8 + gid) * SROW + s * 32 + tig * 4;
#pragma unroll
                    for (int hl = 0; hl < 2; hl++) {
                        bF[j][hl][0] = lds32(base + hl * TILEB);
                        bF[j][hl][1] = lds32(base + hl * TILEB + 16);
                    }
                }
#pragma unroll
                for (int t = 0; t < 2; t++)
#pragma unroll
                    for (int j = 0; j < 4; j++) {
                        float* d = acc[t][nh * 4 + j];
                        mma_bf16(d, aF[t][0], bF[j][0]);   // Ah*Bh
                        mma_bf16(d, aF[t][0], bF[j][1]);   // Ah*Bl
                        mma_bf16(d, aF[t][1], bF[j][0]);   // Al*Bh
                    }
            }
        }

        __syncthreads();
        if (c + 2 < nch) {
            const int k2 = (c + 2) * BK;
            load_chunk(sb + (c & 1) * BUFB, Ahp + k2, Alp + k2, Bhp + k2,
                       Blp + k2, K, tid);
            cpa_commit();
        }
    }

    // Epilogue: bias (+ReLU); fp32 store or bf16 hi/lo split store
#pragma unroll
    for (int t = 0; t < 2; t++) {
        const int r0 = m0 + warp_m * 32 + t * 16 + gid;
        const int r1 = r0 + 8;
#pragma unroll
        for (int nt = 0; nt < 8; nt++) {
            const int col = n0 + warp_n * 64 + nt * 8 + tig * 2;
            const float bv0 = __ldg(&bias[col]);
            const float bv1 = __ldg(&bias[col + 1]);
            float v00 = acc[t][nt][0] + bv0;
            float v01 = acc[t][nt][1] + bv1;
            float v10 = acc[t][nt][2] + bv0;
            float v11 = acc[t][nt][3] + bv1;
            if (doRelu) {
                v00 = fmaxf(v00, 0.0f); v01 = fmaxf(v01, 0.0f);
                v10 = fmaxf(v10, 0.0f); v11 = fmaxf(v11, 0.0f);
            }
            if (!outBf16) {
                *(float2*)(Cf + (size_t)r0 * Ntot + col) = make_float2(v00, v01);
                *(float2*)(Cf + (size_t)r1 * Ntot + col) = make_float2(v10, v11);
            } else {
                __nv_bfloat16 h00, l00, h01, l01, h10, l10, h11, l11;
                split_bf16(v00, h00, l00); split_bf16(v01, h01, l01);
                split_bf16(v10, h10, l10); split_bf16(v11, h11, l11);
                __nv_bfloat162* chp0 = (__nv_bfloat162*)(Ch + (size_t)r0 * Ntot + col);
                __nv_bfloat162* clp0 = (__nv_bfloat162*)(Cl + (size_t)r0 * Ntot + col);
                __nv_bfloat162* chp1 = (__nv_bfloat162*)(Ch + (size_t)r1 * Ntot + col);
                __nv_bfloat162* clp1 = (__nv_bfloat162*)(Cl + (size_t)r1 * Ntot + col);
                *chp0 = __nv_bfloat162(h00, h01);
                *clp0 = __nv_bfloat162(l00, l01);
                *chp1 = __nv_bfloat162(h10, h11);
                *clp1 = __nv_bfloat162(l10, l11);
            }
        }
    }
}

// ---------------------------------------------------------------------------
// Launch
// ---------------------------------------------------------------------------
extern "C" void kernel_launch(void* const* d_in, const int* in_sizes, int n_in,
                              void* d_out, int out_size)
{
    const float* xyz1 = (const float*)d_in[0];
    const float* xyz2 = (const float*)d_in[1];
    const float* f1   = (const float*)d_in[2];
    const float* f2   = (const float*)d_in[3];
    const float* W1   = (const float*)d_in[4];
    const float* b1   = (const float*)d_in[5];
    const float* W2   = (const float*)d_in[6];
    const float* b2   = (const float*)d_in[7];
    const float* W3   = (const float*)d_in[8];
    const float* b3   = (const float*)d_in[9];
    float* out = (float*)d_out;

    void *xh, *xl, *hah, *hal, *hbh, *hbl;
    void *w1h, *w1l, *w2h, *w2l, *w3h, *w3l;
    cudaGetSymbolAddress(&xh,  g_Xh);  cudaGetSymbolAddress(&xl,  g_Xl);
    cudaGetSymbolAddress(&hah, g_Hah); cudaGetSymbolAddress(&hal, g_Hal);
    cudaGetSymbolAddress(&hbh, g_Hbh); cudaGetSymbolAddress(&hbl, g_Hbl);
    cudaGetSymbolAddress(&w1h, g_W1h); cudaGetSymbolAddress(&w1l, g_W1l);
    cudaGetSymbolAddress(&w2h, g_W2h); cudaGetSymbolAddress(&w2l, g_W2l);
    cudaGetSymbolAddress(&w3h, g_W3h); cudaGetSymbolAddress(&w3l, g_W3l);

    typedef __nv_bfloat16 bf;
    bf *Xh=(bf*)xh, *Xl=(bf*)xl, *Hah=(bf*)hah, *Hal=(bf*)hal;
    bf *Hbh=(bf*)hbh, *Hbl=(bf*)hbl;
    bf *W1h=(bf*)w1h, *W1l=(bf*)w1l, *W2h=(bf*)w2h, *W2l=(bf*)w2l;
    bf *W3h=(bf*)w3h, *W3l=(bf*)w3l;

    cudaFuncSetAttribute(gemm_tc, cudaFuncAttributeMaxDynamicSharedMemorySize,
                         GEMM_SMEM);

    dim3 g1(NPTS / 256, BATCH);
    three_nn_kernel<<<g1, 256>>>(xyz1, xyz2);

    build_x_kernel<<<TOTAL, 384>>>(f1, f2);

    prep_w_kernel<<<(CIN * H1DIM + 255) / 256, 256>>>(W1, W1h, W1l, CIN,   H1DIM);
    prep_w_kernel<<<(H1DIM * H2DIM + 255) / 256, 256>>>(W2, W2h, W2l, H1DIM, H2DIM);
    prep_w_kernel<<<(H2DIM * COUT + 255) / 256, 256>>>(W3, W3h, W3l, H2DIM, COUT);

    gemm_tc<<<dim3(H1DIM / BN, TOTAL / BM), 256, GEMM_SMEM>>>(
        Xh, Xl, W1h, W1l, b1, nullptr, Hah, Hal, CIN, H1DIM, 1, 1);
    gemm_tc<<<dim3(H2DIM / BN, TOTAL / BM), 256, GEMM_SMEM>>>(
        Hah, Hal, W2h, W2l, b2, nullptr, Hbh, Hbl, H1DIM, H2DIM, 1, 1);
    gemm_tc<<<dim3(COUT / BN, TOTAL / BM), 256, GEMM_SMEM>>>(
        Hbh, Hbl, W3h, W3l, b3, out, nullptr, nullptr, H2DIM, COUT, 0, 0);
}

// round 7
// speedup vs baseline: 2.6771x; 1.1027x over previous
#include <cuda_runtime.h>
#include <cuda_bf16.h>
#include <cstdint>

// Problem constants (fixed shapes for this dataset)
#define BATCH   4
#define NPTS    16384
#define MPTS    4096
#define C1DIM   128
#define C2DIM   256
#define CIN     384       // C1 + C2
#define H1DIM   256
#define H2DIM   256
#define COUT    128
#define TOTAL   (BATCH * NPTS)   // 65536 points

// ---------------------------------------------------------------------------
// Scratch (static device globals — no runtime allocation allowed)
// ---------------------------------------------------------------------------
__device__ int   g_idx[TOTAL * 3];
__device__ float g_w[TOTAL * 3];
__device__ __align__(256) __nv_bfloat16 g_Xh[(size_t)TOTAL * CIN];
__device__ __align__(256) __nv_bfloat16 g_Xl[(size_t)TOTAL * CIN];
__device__ __align__(256) __nv_bfloat16 g_Hah[(size_t)TOTAL * H1DIM];
__device__ __align__(256) __nv_bfloat16 g_Hal[(size_t)TOTAL * H1DIM];
__device__ __align__(256) __nv_bfloat16 g_Hbh[(size_t)TOTAL * H2DIM];
__device__ __align__(256) __nv_bfloat16 g_Hbl[(size_t)TOTAL * H2DIM];
__device__ __align__(256) __nv_bfloat16 g_W1h[H1DIM * CIN];
__device__ __align__(256) __nv_bfloat16 g_W1l[H1DIM * CIN];
__device__ __align__(256) __nv_bfloat16 g_W2h[H2DIM * H1DIM];
__device__ __align__(256) __nv_bfloat16 g_W2l[H2DIM * H1DIM];
__device__ __align__(256) __nv_bfloat16 g_W3h[COUT * H2DIM];
__device__ __align__(256) __nv_bfloat16 g_W3l[COUT * H2DIM];

// ---------------------------------------------------------------------------
// Small helpers
// ---------------------------------------------------------------------------
__device__ __forceinline__ uint32_t smem_to_u32(const void* p) {
    uint32_t a;
    asm("{ .reg .u64 t; cvta.to.shared.u64 t, %1; cvt.u32.u64 %0, t; }"
        : "=r"(a) : "l"(p));
    return a;
}
__device__ __forceinline__ void cpa16(uint32_t dst, const void* src) {
    asm volatile("cp.async.cg.shared.global [%0], [%1], 16;"
                 :: "r"(dst), "l"(src));
}
__device__ __forceinline__ void cpa_commit() {
    asm volatile("cp.async.commit_group;" ::: "memory");
}
template <int N>
__device__ __forceinline__ void cpa_wait() {
    asm volatile("cp.async.wait_group %0;" :: "n"(N) : "memory");
}
__device__ __forceinline__ void ldsm_x4(uint32_t* r, uint32_t addr) {
    asm volatile("ldmatrix.sync.aligned.m8n8.x4.shared.b16 {%0,%1,%2,%3}, [%4];"
                 : "=r"(r[0]), "=r"(r[1]), "=r"(r[2]), "=r"(r[3]) : "r"(addr));
}
// m16n8k16 row.col bf16 MMA, f32 accumulate
__device__ __forceinline__ void mma_bf16(float* d, const uint32_t* a,
                                         const uint32_t* b) {
    asm("mma.sync.aligned.m16n8k16.row.col.f32.bf16.bf16.f32 "
        "{%0,%1,%2,%3}, {%4,%5,%6,%7}, {%8,%9}, {%0,%1,%2,%3};"
        : "+f"(d[0]), "+f"(d[1]), "+f"(d[2]), "+f"(d[3])
        : "r"(a[0]), "r"(a[1]), "r"(a[2]), "r"(a[3]), "r"(b[0]), "r"(b[1]));
}
// fp32 -> bf16 hi/lo split
__device__ __forceinline__ void split_bf16(float x, __nv_bfloat16& h,
                                           __nv_bfloat16& l) {
    h = __float2bfloat16_rn(x);
    l = __float2bfloat16_rn(x - __bfloat162float(h));
}
// packed f32x2 helpers (sm_100+; proven working on this harness in R3)
__device__ __forceinline__ unsigned long long pk2(float a, float b) {
    unsigned long long r;
    asm("mov.b64 %0, {%1, %2};" : "=l"(r)
        : "r"(__float_as_uint(a)), "r"(__float_as_uint(b)));
    return r;
}
__device__ __forceinline__ unsigned long long add2(unsigned long long a,
                                                   unsigned long long b) {
    unsigned long long r;
    asm("add.rn.f32x2 %0, %1, %2;" : "=l"(r) : "l"(a), "l"(b));
    return r;
}
__device__ __forceinline__ unsigned long long mul2(unsigned long long a,
                                                   unsigned long long b) {
    unsigned long long r;
    asm("mul.rn.f32x2 %0, %1, %2;" : "=l"(r) : "l"(a), "l"(b));
    return r;
}
__device__ __forceinline__ unsigned long long fma2(unsigned long long a,
                                                   unsigned long long b,
                                                   unsigned long long c) {
    unsigned long long r;
    asm("fma.rn.f32x2 %0, %1, %2, %3;" : "=l"(r) : "l"(a), "l"(b), "l"(c));
    return r;
}
__device__ __forceinline__ void unpk2(unsigned long long v, float& lo, float& hi) {
    uint32_t a, b;
    asm("mov.b64 {%0, %1}, %2;" : "=r"(a), "=r"(b) : "l"(v));
    lo = __uint_as_float(a);
    hi = __uint_as_float(b);
}

// ---------------------------------------------------------------------------
// Kernel 1: three_nn + interpolation weights (f32x2-packed candidate loop)
// ---------------------------------------------------------------------------
__device__ __forceinline__ void upd3(float d, int j,
                                     float& d0, float& d1, float& d2,
                                     int& i0, int& i1, int& i2) {
    if (d < d2) {
        if (d < d1) {
            d2 = d1; i2 = i1;
            if (d < d0) { d1 = d0; i1 = i0; d0 = d; i0 = j; }
            else        { d1 = d;  i1 = j; }
        } else {
            d2 = d; i2 = j;
        }
    }
}

__global__ __launch_bounds__(256) void three_nn_kernel(
    const float* __restrict__ xyz1, const float* __restrict__ xyz2)
{
    // negated xyz2 coords, accessed as packed float pairs
    __shared__ __align__(8) float snx[MPTS];
    __shared__ __align__(8) float sny[MPTS];
    __shared__ __align__(8) float snz[MPTS];

    const int b = blockIdx.y;
    const float* p2 = xyz2 + (size_t)b * MPTS * 3;
    for (int j = threadIdx.x; j < MPTS; j += 256) {
        snx[j] = -p2[3 * j + 0];
        sny[j] = -p2[3 * j + 1];
        snz[j] = -p2[3 * j + 2];
    }
    __syncthreads();

    const int n = blockIdx.x * 256 + threadIdx.x;
    const float* p1 = xyz1 + ((size_t)b * NPTS + n) * 3;
    const float x = p1[0], y = p1[1], z = p1[2];
    const unsigned long long x2 = pk2(x, x);
    const unsigned long long y2 = pk2(y, y);
    const unsigned long long z2 = pk2(z, z);

    float d0 = 1e30f, d1 = 1e30f, d2 = 1e30f;
    int   i0 = 0, i1 = 0, i2 = 0;

    const unsigned long long* nxp = (const unsigned long long*)snx;
    const unsigned long long* nyp = (const unsigned long long*)sny;
    const unsigned long long* nzp = (const unsigned long long*)snz;

#pragma unroll 4
    for (int p = 0; p < MPTS / 2; p++) {
        unsigned long long dx = add2(x2, nxp[p]);
        unsigned long long dy = add2(y2, nyp[p]);
        unsigned long long dz = add2(z2, nzp[p]);
        unsigned long long dd = mul2(dx, dx);
        dd = fma2(dy, dy, dd);
        dd = fma2(dz, dz, dd);
        float lo, hi;
        unpk2(dd, lo, hi);
        if (fminf(lo, hi) < d2) {
            upd3(lo, 2 * p,     d0, d1, d2, i0, i1, i2);
            upd3(hi, 2 * p + 1, d0, d1, d2, i0, i1, i2);
        }
    }

    float r0 = 1.0f / fmaxf(d0, 1e-10f);
    float r1 = 1.0f / fmaxf(d1, 1e-10f);
    float r2 = 1.0f / fmaxf(d2, 1e-10f);
    float s = 1.0f / (r0 + r1 + r2);

    size_t o = ((size_t)b * NPTS + n) * 3;
    g_idx[o + 0] = i0; g_idx[o + 1] = i1; g_idx[o + 2] = i2;
    g_w[o + 0] = r0 * s; g_w[o + 1] = r1 * s; g_w[o + 2] = r2 * s;
}

// ---------------------------------------------------------------------------
// Kernel 2: build X = concat(features1, interp(features2)), split to bf16 h/l
// ---------------------------------------------------------------------------
__global__ __launch_bounds__(384) void build_x_kernel(
    const float* __restrict__ f1, const float* __restrict__ f2)
{
    const int p = blockIdx.x;
    const int t = threadIdx.x;
    float v;

    if (t < C1DIM) {
        v = f1[(size_t)p * C1DIM + t];
    } else {
        const int c = t - C1DIM;
        const int b = p >> 14;
        const size_t o = (size_t)p * 3;
        const int i0 = g_idx[o], i1 = g_idx[o + 1], i2 = g_idx[o + 2];
        const float w0 = g_w[o], w1 = g_w[o + 1], w2 = g_w[o + 2];
        const float* base = f2 + (size_t)b * MPTS * C2DIM;
        v = w0 * base[(size_t)i0 * C2DIM + c]
          + w1 * base[(size_t)i1 * C2DIM + c]
          + w2 * base[(size_t)i2 * C2DIM + c];
    }
    __nv_bfloat16 h, l;
    split_bf16(v, h, l);
    g_Xh[(size_t)p * CIN + t] = h;
    g_Xl[(size_t)p * CIN + t] = l;
}

// ---------------------------------------------------------------------------
// Kernel 2b: weight prep — transpose [K,N]->[N,K] and split to bf16 h/l
// ---------------------------------------------------------------------------
__global__ void prep_w_kernel(const float* __restrict__ W,
                              __nv_bfloat16* __restrict__ Wh,
                              __nv_bfloat16* __restrict__ Wl, int K, int N)
{
    int i = blockIdx.x * 256 + threadIdx.x;
    if (i < N * K) {
        int n = i / K, k = i - n * K;
        __nv_bfloat16 h, l;
        split_bf16(W[(size_t)k * N + n], h, l);
        Wh[i] = h; Wl[i] = l;
    }
}

// ---------------------------------------------------------------------------
// Kernel 3: bf16 HMMA GEMM (mma.sync m16n8k16), 3-pass fp32 emulation,
// ldmatrix fragment loads.
// C[M,Ntot] = A[M,K] @ Bt[Ntot,K]^T + bias (opt ReLU).
// A = Ah + Al, B = Bh + Bl (bf16);  D = AhBh + AhBl + AlBh.
// CTA 128x128, BK=32, 8 warps (4m x 2n), warp tile 32x64.
// smem row stride 80B -> conflict-free for both cp.async and ldmatrix.
// ---------------------------------------------------------------------------
#define BM 128
#define BN 128
#define BK 32
#define SROW 80                       // bytes per smem row (32 bf16 + pad)
#define TILEB (128 * SROW)            // 10240 per operand tile
#define BUFB  (4 * TILEB)             // Ah, Al, Bh, Bl per buffer
#define GEMM_SMEM (2 * BUFB)          // 81920

__device__ __forceinline__ void load_chunk(
    uint32_t sbuf,
    const __nv_bfloat16* __restrict__ Ah, const __nv_bfloat16* __restrict__ Al,
    const __nv_bfloat16* __restrict__ Bh, const __nv_bfloat16* __restrict__ Bl,
    int K, int tid)
{
    const int row = tid >> 2;         // 0..63
    const int piece = tid & 3;        // 0..3 (16B each, 64B row payload)
    const uint32_t d0 = row * SROW + piece * 16;
    const size_t g0 = (size_t)row * K + piece * 8;
    const uint32_t d1 = d0 + 64 * SROW;
    const size_t g1 = g0 + (size_t)64 * K;

    cpa16(sbuf + 0 * TILEB + d0, Ah + g0);
    cpa16(sbuf + 1 * TILEB + d0, Al + g0);
    cpa16(sbuf + 2 * TILEB + d0, Bh + g0);
    cpa16(sbuf + 3 * TILEB + d0, Bl + g0);
    cpa16(sbuf + 0 * TILEB + d1, Ah + g1);
    cpa16(sbuf + 1 * TILEB + d1, Al + g1);
    cpa16(sbuf + 2 * TILEB + d1, Bh + g1);
    cpa16(sbuf + 3 * TILEB + d1, Bl + g1);
}

__global__ __launch_bounds__(256, 2) void gemm_tc(
    const __nv_bfloat16* __restrict__ Ah, const __nv_bfloat16* __restrict__ Al,
    const __nv_bfloat16* __restrict__ Bh, const __nv_bfloat16* __restrict__ Bl,
    const float* __restrict__ bias,
    float* __restrict__ Cf,
    __nv_bfloat16* __restrict__ Ch, __nv_bfloat16* __restrict__ Cl,
    int K, int Ntot, int doRelu, int outBf16)
{
    extern __shared__ char smem[];
    const uint32_t sb = smem_to_u32(smem);
    const int tid = threadIdx.x;
    const int wid = tid >> 5;
    const int lane = tid & 31;
    const int gid = lane >> 2;        // 0..7
    const int tig = lane & 3;         // 0..3
    const int warp_m = wid >> 1;      // 0..3
    const int warp_n = wid & 1;       // 0..1
    const int m0 = blockIdx.y * BM;
    const int n0 = blockIdx.x * BN;

    const __nv_bfloat16* Ahp = Ah + (size_t)m0 * K;
    const __nv_bfloat16* Alp = Al + (size_t)m0 * K;
    const __nv_bfloat16* Bhp = Bh + (size_t)n0 * K;
    const __nv_bfloat16* Blp = Bl + (size_t)n0 * K;

    float acc[2][8][4];
#pragma unroll
    for (int t = 0; t < 2; t++)
#pragma unroll
        for (int nt = 0; nt < 8; nt++)
#pragma unroll
            for (int r = 0; r < 4; r++) acc[t][nt][r] = 0.0f;

    const int nch = K / BK;

    // per-lane ldmatrix address components (relative; add sA/sB + s*32)
    // A: rows = warp_m*32 + t*16 + (lane&15); col byte = ((lane>>4)<<4)
    const uint32_t a_rel = (uint32_t)((warp_m * 32 + (lane & 15)) * SROW
                                      + ((lane >> 4) << 4));
    // B: rows = warp_n*64 + npair*16 + ((lane>>4)<<3) + (lane&7);
    //    col byte = (((lane>>3)&1)<<4)
    const uint32_t b_rel = (uint32_t)((warp_n * 64 + ((lane >> 4) << 3)
                                       + (lane & 7)) * SROW
                                      + (((lane >> 3) & 1) << 4));

    // prologue: prefetch chunks 0 and 1
    load_chunk(sb, Ahp, Alp, Bhp, Blp, K, tid);
    cpa_commit();
    if (nch > 1) {
        load_chunk(sb + BUFB, Ahp + BK, Alp + BK, Bhp + BK, Blp + BK, K, tid);
        cpa_commit();
    }

    for (int c = 0; c < nch; c++) {
        if (c + 1 < nch) cpa_wait<1>(); else cpa_wait<0>();
        __syncthreads();

        const uint32_t sA = sb + (c & 1) * BUFB;
        const uint32_t sB = sA + 2 * TILEB;

#pragma unroll
        for (int s = 0; s < 2; s++) {             // two k16 steps per chunk
            // A fragments: 2 m-tiles x (hi,lo), each one ldmatrix.x4
            uint32_t aF[2][2][4];
#pragma unroll
            for (int t = 0; t < 2; t++)
#pragma unroll
                for (int hl = 0; hl < 2; hl++)
                    ldsm_x4(aF[t][hl],
                            sA + hl * TILEB + a_rel + t * (16 * SROW) + s * 32);

#pragma unroll
            for (int np = 0; np < 4; np++) {      // pairs of n8 tiles
                uint32_t bh[4], bl[4];
                const uint32_t ba = sB + b_rel + np * (16 * SROW) + s * 32;
                ldsm_x4(bh, ba);                  // hi: {tile0 b0,b1, tile1 b0,b1}
                ldsm_x4(bl, ba + TILEB);          // lo
#pragma unroll
                for (int t = 0; t < 2; t++) {
                    float* e0 = acc[t][np * 2];
                    float* e1 = acc[t][np * 2 + 1];
                    mma_bf16(e0, aF[t][0], bh + 0);   // Ah*Bh
                    mma_bf16(e0, aF[t][0], bl + 0);   // Ah*Bl
                    mma_bf16(e0, aF[t][1], bh + 0);   // Al*Bh
                    mma_bf16(e1, aF[t][0], bh + 2);
                    mma_bf16(e1, aF[t][0], bl + 2);
                    mma_bf16(e1, aF[t][1], bh + 2);
                }
            }
        }

        __syncthreads();
        if (c + 2 < nch) {
            const int k2 = (c + 2) * BK;
            load_chunk(sb + (c & 1) * BUFB, Ahp + k2, Alp + k2, Bhp + k2,
                       Blp + k2, K, tid);
            cpa_commit();
        }
    }

    // Epilogue: bias (+ReLU); fp32 store or bf16 hi/lo split store
#pragma unroll
    for (int t = 0; t < 2; t++) {
        const int r0 = m0 + warp_m * 32 + t * 16 + gid;
        const int r1 = r0 + 8;
#pragma unroll
        for (int nt = 0; nt < 8; nt++) {
            const int col = n0 + warp_n * 64 + nt * 8 + tig * 2;
            const float bv0 = __ldg(&bias[col]);
            const float bv1 = __ldg(&bias[col + 1]);
            float v00 = acc[t][nt][0] + bv0;
            float v01 = acc[t][nt][1] + bv1;
            float v10 = acc[t][nt][2] + bv0;
            float v11 = acc[t][nt][3] + bv1;
            if (doRelu) {
                v00 = fmaxf(v00, 0.0f); v01 = fmaxf(v01, 0.0f);
                v10 = fmaxf(v10, 0.0f); v11 = fmaxf(v11, 0.0f);
            }
            if (!outBf16) {
                *(float2*)(Cf + (size_t)r0 * Ntot + col) = make_float2(v00, v01);
                *(float2*)(Cf + (size_t)r1 * Ntot + col) = make_float2(v10, v11);
            } else {
                __nv_bfloat16 h00, l00, h01, l01, h10, l10, h11, l11;
                split_bf16(v00, h00, l00); split_bf16(v01, h01, l01);
                split_bf16(v10, h10, l10); split_bf16(v11, h11, l11);
                __nv_bfloat162* chp0 = (__nv_bfloat162*)(Ch + (size_t)r0 * Ntot + col);
                __nv_bfloat162* clp0 = (__nv_bfloat162*)(Cl + (size_t)r0 * Ntot + col);
                __nv_bfloat162* chp1 = (__nv_bfloat162*)(Ch + (size_t)r1 * Ntot + col);
                __nv_bfloat162* clp1 = (__nv_bfloat162*)(Cl + (size_t)r1 * Ntot + col);
                *chp0 = __nv_bfloat162(h00, h01);
                *clp0 = __nv_bfloat162(l00, l01);
                *chp1 = __nv_bfloat162(h10, h11);
                *clp1 = __nv_bfloat162(l10, l11);
            }
        }
    }
}

// ---------------------------------------------------------------------------
// Launch
// ---------------------------------------------------------------------------
extern "C" void kernel_launch(void* const* d_in, const int* in_sizes, int n_in,
                              void* d_out, int out_size)
{
    const float* xyz1 = (const float*)d_in[0];
    const float* xyz2 = (const float*)d_in[1];
    const float* f1   = (const float*)d_in[2];
    const float* f2   = (const float*)d_in[3];
    const float* W1   = (const float*)d_in[4];
    const float* b1   = (const float*)d_in[5];
    const float* W2   = (const float*)d_in[6];
    const float* b2   = (const float*)d_in[7];
    const float* W3   = (const float*)d_in[8];
    const float* b3   = (const float*)d_in[9];
    float* out = (float*)d_out;

    void *xh, *xl, *hah, *hal, *hbh, *hbl;
    void *w1h, *w1l, *w2h, *w2l, *w3h, *w3l;
    cudaGetSymbolAddress(&xh,  g_Xh);  cudaGetSymbolAddress(&xl,  g_Xl);
    cudaGetSymbolAddress(&hah, g_Hah); cudaGetSymbolAddress(&hal, g_Hal);
    cudaGetSymbolAddress(&hbh, g_Hbh); cudaGetSymbolAddress(&hbl, g_Hbl);
    cudaGetSymbolAddress(&w1h, g_W1h); cudaGetSymbolAddress(&w1l, g_W1l);
    cudaGetSymbolAddress(&w2h, g_W2h); cudaGetSymbolAddress(&w2l, g_W2l);
    cudaGetSymbolAddress(&w3h, g_W3h); cudaGetSymbolAddress(&w3l, g_W3l);

    typedef __nv_bfloat16 bf;
    bf *Xh=(bf*)xh, *Xl=(bf*)xl, *Hah=(bf*)hah, *Hal=(bf*)hal;
    bf *Hbh=(bf*)hbh, *Hbl=(bf*)hbl;
    bf *W1h=(bf*)w1h, *W1l=(bf*)w1l, *W2h=(bf*)w2h, *W2l=(bf*)w2l;
    bf *W3h=(bf*)w3h, *W3l=(bf*)w3l;

    cudaFuncSetAttribute(gemm_tc, cudaFuncAttributeMaxDynamicSharedMemorySize,
                         GEMM_SMEM);

    dim3 g1(NPTS / 256, BATCH);
    three_nn_kernel<<<g1, 256>>>(xyz1, xyz2);

    build_x_kernel<<<TOTAL, 384>>>(f1, f2);

    prep_w_kernel<<<(CIN * H1DIM + 255) / 256, 256>>>(W1, W1h, W1l, CIN,   H1DIM);
    prep_w_kernel<<<(H1DIM * H2DIM + 255) / 256, 256>>>(W2, W2h, W2l, H1DIM, H2DIM);
    prep_w_kernel<<<(H2DIM * COUT + 255) / 256, 256>>>(W3, W3h, W3l, H2DIM, COUT);

    gemm_tc<<<dim3(H1DIM / BN, TOTAL / BM), 256, GEMM_SMEM>>>(
        Xh, Xl, W1h, W1l, b1, nullptr, Hah, Hal, CIN, H1DIM, 1, 1);
    gemm_tc<<<dim3(H2DIM / BN, TOTAL / BM), 256, GEMM_SMEM>>>(
        Hah, Hal, W2h, W2l, b2, nullptr, Hbh, Hbl, H1DIM, H2DIM, 1, 1);
    gemm_tc<<<dim3(COUT / BN, TOTAL / BM), 256, GEMM_SMEM>>>(
        Hbh, Hbl, W3h, W3l, b3, out, nullptr, nullptr, H2DIM, COUT, 0, 0);
}